// round 1
// baseline (speedup 1.0000x reference)
#include <cuda_runtime.h>
#include <cuda_bf16.h>
#include <cstdint>

#define BB 4
#define NN 4096
#define MM 4096
#define MT 256            // threads per block == m's per block
#define NT 512            // n's per chunk
#define NCHUNK (NN / NT)  // 8

#define EPSF     1e-8f
#define INV_LN2  1.4426950408889634f
#define LN2F     0.6931471805599453f
// 1.5 * ln(2*3.14159)  (reference uses pi = 3.14159)
#define C_OFF    2.7568143383208773f

__device__ float4 g_prepA[BB * NN];   // px, py, pz, a
__device__ float2 g_prepB[BB * NN];   // bz, c
__device__ float  g_part[NCHUNK][BB * MM];

// ---------------- prep: per-(b,n) derived coefficients ----------------
__global__ void prep_kernel(const float* __restrict__ xyz,
                            const float* __restrict__ sig) {
    int i = blockIdx.x * blockDim.x + threadIdx.x;   // 0 .. BB*NN-1
    if (i >= BB * NN) return;
    float px = xyz[3 * i + 0];
    float py = xyz[3 * i + 1];
    float pz = xyz[3 * i + 2];
    float sxy = sig[2 * i + 0] + EPSF;
    float sz  = sig[2 * i + 1] + EPSF;
    float a  = 0.5f * INV_LN2 / sxy;
    float bz = 0.5f * INV_LN2 / sz;
    // c = (-log(sxy) - 0.5*log(sz) - 1.5*LOG_2PI) / ln2
    float c = (-logf(sxy) - 0.5f * logf(sz) - C_OFF) * INV_LN2;
    g_prepA[i] = make_float4(px, py, pz, a);
    g_prepB[i] = make_float2(bz, c);
}

// fast 2^x on the FMA/ALU pipes (no MUFU). Valid for x <= ~60; x clamped
// below at -126 so the scale exponent stays in normal range (result ~0).
__device__ __forceinline__ float fast_exp2(float x) {
    x = fmaxf(x, -126.0f);
    float t  = x + 12582912.0f;            // 2^23 + 2^22 : round-to-nearest-int
    float fi = t - 12582912.0f;            // integer-valued float
    float f  = x - fi;                     // [-0.5, 0.5]
    unsigned sb = (__float_as_uint(t) + 127u) << 23;   // 2^i bits
    // degree-5 Taylor of 2^f = exp(f*ln2) on [-0.5, 0.5]; max err ~2.4e-6
    float p = 0.0013333558146428443f;
    p = fmaf(p, f, 0.009618129107628477f);
    p = fmaf(p, f, 0.05550410866482158f);
    p = fmaf(p, f, 0.24022650695910072f);
    p = fmaf(p, f, 0.6931471805599453f);
    p = fmaf(p, f, 1.0f);
    return p * __uint_as_float(sb);
}

// ---------------- main: partial sum of exp over one n-chunk ----------------
__global__ __launch_bounds__(MT) void gmm_main_kernel(const float* __restrict__ target) {
    __shared__ float4 sA[NT];
    __shared__ float2 sB[NT];

    const int mt = blockIdx.x;     // 0..MM/MT-1
    const int ch = blockIdx.y;     // 0..NCHUNK-1
    const int b  = blockIdx.z;     // 0..BB-1

    const int m = mt * MT + threadIdx.x;
    const float* tp = target + ((size_t)b * MM + m) * 3;
    const float tx = tp[0], ty = tp[1], tz = tp[2];

    const int nbase = b * NN + ch * NT;
    for (int j = threadIdx.x; j < NT; j += MT) {
        sA[j] = g_prepA[nbase + j];
        sB[j] = g_prepB[nbase + j];
    }
    __syncthreads();

    float sum0 = 0.0f, sum1 = 0.0f;
#pragma unroll 8
    for (int j = 0; j < NT; j += 2) {
        {
            float4 A = sA[j];
            float2 Bv = sB[j];
            float dx = A.x - tx, dy = A.y - ty, dz = A.z - tz;
            float d2 = fmaf(dy, dy, dx * dx);
            float x  = fmaf(-A.w, d2, Bv.y);
            x = fmaf(-Bv.x * dz, dz, x);
            sum0 += fast_exp2(x);
        }
        {
            float4 A = sA[j + 1];
            float2 Bv = sB[j + 1];
            float dx = A.x - tx, dy = A.y - ty, dz = A.z - tz;
            float d2 = fmaf(dy, dy, dx * dx);
            float x  = fmaf(-A.w, d2, Bv.y);
            x = fmaf(-Bv.x * dz, dz, x);
            sum1 += fast_exp2(x);
        }
    }
    g_part[ch][b * MM + m] = sum0 + sum1;
}

// ---------------- final: combine chunks, log, mean ----------------
__global__ void gmm_final_kernel(float* __restrict__ out) {
    __shared__ float red[256];
    const int tid = threadIdx.x;
    float acc = 0.0f;
    for (int i = tid; i < BB * MM; i += 256) {
        float s = 0.0f;
#pragma unroll
        for (int c = 0; c < NCHUNK; c++) s += g_part[c][i];
        // sum of 2^(lp/ln2) == sum of e^lp ; nll = -ln(sum)
        acc += -(__logf(s));
    }
    red[tid] = acc;
    __syncthreads();
    for (int s = 128; s > 0; s >>= 1) {
        if (tid < s) red[tid] += red[tid + s];
        __syncthreads();
    }
    if (tid == 0) out[0] = red[0] * (1.0f / (BB * MM));
}

extern "C" void kernel_launch(void* const* d_in, const int* in_sizes, int n_in,
                              void* d_out, int out_size) {
    const float* pred_xyz   = (const float*)d_in[0];  // [B, N, 3]
    const float* pred_sigma = (const float*)d_in[1];  // [B, N, 2]
    const float* target     = (const float*)d_in[2];  // [B, M, 3]
    float* out = (float*)d_out;

    prep_kernel<<<(BB * NN + 255) / 256, 256>>>(pred_xyz, pred_sigma);

    dim3 grid(MM / MT, NCHUNK, BB);
    gmm_main_kernel<<<grid, MT>>>(target);

    gmm_final_kernel<<<1, 256>>>(out);
}

// round 2
// speedup vs baseline: 1.0180x; 1.0180x over previous
#include <cuda_runtime.h>
#include <cuda_bf16.h>
#include <cstdint>

typedef unsigned long long u64;

#define BB 4
#define NN 4096
#define MM 4096
#define MT 256            // threads per block == m's per block
#define NT 256            // n's per chunk
#define NQ (NT / 2)       // packed pairs per chunk
#define NCHUNK (NN / NT)  // 16

#define EPSF     1e-8f
#define INV_LN2  1.4426950408889634f
// 1.5 * ln(2*3.14159)  (reference uses pi = 3.14159)
#define C_OFF    2.7568143383208773f

// packed pair prep:  A = {px01, py01}   B = {pz01, na01}   C = {nbz01, c01}
__device__ ulonglong2 g_A[BB * NN / 2];
__device__ ulonglong2 g_B[BB * NN / 2];
__device__ ulonglong2 g_C[BB * NN / 2];
__device__ float g_part[NCHUNK][BB * MM];

// ---------------- packed f32x2 primitives ----------------
#define ADD2(d, a, b)    asm("add.rn.f32x2 %0, %1, %2;"      : "=l"(d) : "l"(a), "l"(b))
#define MUL2(d, a, b)    asm("mul.rn.f32x2 %0, %1, %2;"      : "=l"(d) : "l"(a), "l"(b))
#define FMA2(d, a, b, c) asm("fma.rn.f32x2 %0, %1, %2, %3;"  : "=l"(d) : "l"(a), "l"(b), "l"(c))

__device__ __forceinline__ u64 pk(float lo, float hi) {
    u64 r;
    asm("mov.b64 %0, {%1, %2};" : "=l"(r) : "f"(lo), "f"(hi));
    return r;
}

// ---------------- prep: per-(b, n-pair) derived coefficients ----------------
__global__ void prep_kernel(const float* __restrict__ xyz,
                            const float* __restrict__ sig) {
    int q = blockIdx.x * blockDim.x + threadIdx.x;   // 0 .. BB*NN/2-1
    if (q >= BB * NN / 2) return;
    int i0 = 2 * q, i1 = 2 * q + 1;

    float px0 = xyz[3 * i0 + 0], py0 = xyz[3 * i0 + 1], pz0 = xyz[3 * i0 + 2];
    float px1 = xyz[3 * i1 + 0], py1 = xyz[3 * i1 + 1], pz1 = xyz[3 * i1 + 2];
    float sxy0 = sig[2 * i0 + 0] + EPSF, sz0 = sig[2 * i0 + 1] + EPSF;
    float sxy1 = sig[2 * i1 + 0] + EPSF, sz1 = sig[2 * i1 + 1] + EPSF;

    float na0  = -0.5f * INV_LN2 / sxy0;
    float na1  = -0.5f * INV_LN2 / sxy1;
    float nbz0 = -0.5f * INV_LN2 / sz0;
    float nbz1 = -0.5f * INV_LN2 / sz1;
    float c0 = (-logf(sxy0) - 0.5f * logf(sz0) - C_OFF) * INV_LN2;
    float c1 = (-logf(sxy1) - 0.5f * logf(sz1) - C_OFF) * INV_LN2;

    ulonglong2 A, B, C;
    A.x = pk(px0, px1);  A.y = pk(py0, py1);
    B.x = pk(pz0, pz1);  B.y = pk(na0, na1);
    C.x = pk(nbz0, nbz1); C.y = pk(c0, c1);
    g_A[q] = A; g_B[q] = B; g_C[q] = C;
}

// ---------------- main: partial sum of exp over one n-chunk ----------------
__global__ __launch_bounds__(MT) void gmm_main_kernel(const float* __restrict__ target) {
    __shared__ ulonglong2 sA[NQ], sB[NQ], sC[NQ];

    const int mt = blockIdx.x;     // 0..MM/MT-1
    const int ch = blockIdx.y;     // 0..NCHUNK-1
    const int b  = blockIdx.z;     // 0..BB-1

    const int m = mt * MT + threadIdx.x;
    const float* tp = target + ((size_t)b * MM + m) * 3;
    const float tx = tp[0], ty = tp[1], tz = tp[2];
    const u64 nX = pk(-tx, -tx), nY = pk(-ty, -ty), nZ = pk(-tz, -tz);

    const int qbase = (b * NN + ch * NT) / 2;
    for (int j = threadIdx.x; j < NQ; j += MT) {
        sA[j] = g_A[qbase + j];
        sB[j] = g_B[qbase + j];
        sC[j] = g_C[qbase + j];
    }
    __syncthreads();

    // packed constants
    const u64 MAG  = pk(12582912.0f, 12582912.0f);    // 2^23 + 2^22
    const u64 NMAG = pk(-12582912.0f, -12582912.0f);
    const u64 NONE = pk(-1.0f, -1.0f);
    const u64 C4 = pk(0.009618129107628477f, 0.009618129107628477f);
    const u64 C3 = pk(0.05550410866482158f,  0.05550410866482158f);
    const u64 C2 = pk(0.24022650695910072f,  0.24022650695910072f);
    const u64 C1 = pk(0.6931471805599453f,   0.6931471805599453f);
    const u64 ONE = pk(1.0f, 1.0f);

    float s0 = 0.0f, s1 = 0.0f;

#pragma unroll 4
    for (int j = 0; j < NQ; j++) {
        ulonglong2 A = sA[j], B = sB[j], C = sC[j];
        u64 dx, dy, dz, d2, e2, x, t, fi, f, p;

        ADD2(dx, A.x, nX);                // px - tx   (pair)
        ADD2(dy, A.y, nY);
        ADD2(dz, B.x, nZ);
        MUL2(d2, dx, dx);
        FMA2(d2, dy, dy, d2);             // dist_xy
        FMA2(x,  B.y, d2, C.y);           // -a*dxy + c
        MUL2(e2, dz, dz);
        FMA2(x,  C.x, e2, x);             // -bz*dz^2

        // packed 2^x: magic-number range reduction, all on fma pipe
        ADD2(t,  x, MAG);                 // rn -> nearest int in mantissa
        ADD2(fi, t, NMAG);                // integer-valued float
        FMA2(f,  fi, NONE, x);            // f = x - fi  in [-0.5, 0.5]
        FMA2(p, C4, f, C3);
        FMA2(p, p,  f, C2);
        FMA2(p, p,  f, C1);
        FMA2(p, p,  f, ONE);

        // exponent scale on the ALU pipe; clamp handles all x < -127
        // (for x far outside the magic window bits(t) < threshold -> e <= 0)
        unsigned lo = (unsigned)t;
        unsigned hi = (unsigned)(t >> 32);
        int e0 = (int)(lo - 0x4B3FFF81u);         // k + 127
        int e1 = (int)(hi - 0x4B3FFF81u);
        e0 = e0 < 0 ? 0 : e0;
        e1 = e1 < 0 ? 0 : e1;
        float sc0 = __uint_as_float((unsigned)e0 << 23);
        float sc1 = __uint_as_float((unsigned)e1 << 23);

        float plo = __uint_as_float((unsigned)p);
        float phi = __uint_as_float((unsigned)(p >> 32));
        s0 = fmaf(plo, sc0, s0);          // p * 2^k, accumulated
        s1 = fmaf(phi, sc1, s1);
    }
    g_part[ch][b * MM + m] = s0 + s1;
}

// ---------------- final: combine chunks, log, mean ----------------
__global__ void gmm_final_kernel(float* __restrict__ out) {
    __shared__ float red[256];
    const int tid = threadIdx.x;
    float acc = 0.0f;
    for (int i = tid; i < BB * MM; i += 256) {
        float s = 0.0f;
#pragma unroll
        for (int c = 0; c < NCHUNK; c++) s += g_part[c][i];
        acc += -(__logf(s));              // nll = -ln(sum e^lp)
    }
    red[tid] = acc;
    __syncthreads();
    for (int s = 128; s > 0; s >>= 1) {
        if (tid < s) red[tid] += red[tid + s];
        __syncthreads();
    }
    if (tid == 0) out[0] = red[0] * (1.0f / (BB * MM));
}

extern "C" void kernel_launch(void* const* d_in, const int* in_sizes, int n_in,
                              void* d_out, int out_size) {
    const float* pred_xyz   = (const float*)d_in[0];  // [B, N, 3]
    const float* pred_sigma = (const float*)d_in[1];  // [B, N, 2]
    const float* target     = (const float*)d_in[2];  // [B, M, 3]
    float* out = (float*)d_out;

    prep_kernel<<<(BB * NN / 2 + 255) / 256, 256>>>(pred_xyz, pred_sigma);

    dim3 grid(MM / MT, NCHUNK, BB);
    gmm_main_kernel<<<grid, MT>>>(target);

    gmm_final_kernel<<<1, 256>>>(out);
}

// round 4
// speedup vs baseline: 1.5271x; 1.5000x over previous
#include <cuda_runtime.h>
#include <cuda_bf16.h>
#include <cstdint>

typedef unsigned long long u64;

#define BB 4
#define NN 4096
#define MM 4096
#define MT 256            // threads per block == m's per block
#define NT 256            // n's per chunk
#define NQ (NT / 2)       // packed pairs per chunk
#define NCHUNK (NN / NT)  // 16
#define RED_BLOCKS 64

#define EPSF     1e-8f
#define INV_LN2  1.4426950408889634f
// 1.5 * ln(2*3.14159)  (reference uses pi = 3.14159)
#define C_OFF    2.7568143383208773f

// packed pair prep:  A = {px01, py01}   B = {pz01, na01}   C = {nbz01, c01}
__device__ ulonglong2 g_A[BB * NN / 2];
__device__ ulonglong2 g_B[BB * NN / 2];
__device__ ulonglong2 g_C[BB * NN / 2];
__device__ float g_part[NCHUNK][BB * MM];
__device__ float g_red[RED_BLOCKS];

// ---------------- packed f32x2 primitives ----------------
#define ADD2(d, a, b)    asm("add.rn.f32x2 %0, %1, %2;"      : "=l"(d) : "l"(a), "l"(b))
#define MUL2(d, a, b)    asm("mul.rn.f32x2 %0, %1, %2;"      : "=l"(d) : "l"(a), "l"(b))
#define FMA2(d, a, b, c) asm("fma.rn.f32x2 %0, %1, %2, %3;"  : "=l"(d) : "l"(a), "l"(b), "l"(c))

__device__ __forceinline__ u64 pk(float lo, float hi) {
    u64 r;
    asm("mov.b64 %0, {%1, %2};" : "=l"(r) : "f"(lo), "f"(hi));
    return r;
}

// ---------------- prep: per-(b, n-pair) derived coefficients ----------------
__global__ void prep_kernel(const float* __restrict__ xyz,
                            const float* __restrict__ sig) {
    int q = blockIdx.x * blockDim.x + threadIdx.x;   // 0 .. BB*NN/2-1
    if (q >= BB * NN / 2) return;
    int i0 = 2 * q, i1 = 2 * q + 1;

    float px0 = xyz[3 * i0 + 0], py0 = xyz[3 * i0 + 1], pz0 = xyz[3 * i0 + 2];
    float px1 = xyz[3 * i1 + 0], py1 = xyz[3 * i1 + 1], pz1 = xyz[3 * i1 + 2];
    float sxy0 = sig[2 * i0 + 0] + EPSF, sz0 = sig[2 * i0 + 1] + EPSF;
    float sxy1 = sig[2 * i1 + 0] + EPSF, sz1 = sig[2 * i1 + 1] + EPSF;

    float na0  = -0.5f * INV_LN2 / sxy0;
    float na1  = -0.5f * INV_LN2 / sxy1;
    float nbz0 = -0.5f * INV_LN2 / sz0;
    float nbz1 = -0.5f * INV_LN2 / sz1;
    float c0 = (-__logf(sxy0) - 0.5f * __logf(sz0) - C_OFF) * INV_LN2;
    float c1 = (-__logf(sxy1) - 0.5f * __logf(sz1) - C_OFF) * INV_LN2;

    ulonglong2 A, B, C;
    A.x = pk(px0, px1);  A.y = pk(py0, py1);
    B.x = pk(pz0, pz1);  B.y = pk(na0, na1);
    C.x = pk(nbz0, nbz1); C.y = pk(c0, c1);
    g_A[q] = A; g_B[q] = B; g_C[q] = C;
}

// ---------------- main: partial sum of exp over one n-chunk ----------------
__global__ __launch_bounds__(MT) void gmm_main_kernel(const float* __restrict__ target) {
    __shared__ ulonglong2 sA[NQ], sB[NQ], sC[NQ];

    const int mt = blockIdx.x;     // 0..MM/MT-1
    const int ch = blockIdx.y;     // 0..NCHUNK-1
    const int b  = blockIdx.z;     // 0..BB-1

    const int m = mt * MT + threadIdx.x;
    const float* tp = target + ((size_t)b * MM + m) * 3;
    const float tx = tp[0], ty = tp[1], tz = tp[2];
    const u64 nX = pk(-tx, -tx), nY = pk(-ty, -ty), nZ = pk(-tz, -tz);

    const int qbase = (b * NN + ch * NT) / 2;
    for (int j = threadIdx.x; j < NQ; j += MT) {
        sA[j] = g_A[qbase + j];
        sB[j] = g_B[qbase + j];
        sC[j] = g_C[qbase + j];
    }
    __syncthreads();

    // packed constants
    const u64 MAG  = pk(12582912.0f, 12582912.0f);    // 2^23 + 2^22
    const u64 NMAG = pk(-12582912.0f, -12582912.0f);
    const u64 NONE = pk(-1.0f, -1.0f);
    const u64 C4 = pk(0.009618129107628477f, 0.009618129107628477f);
    const u64 C3 = pk(0.05550410866482158f,  0.05550410866482158f);
    const u64 C2 = pk(0.24022650695910072f,  0.24022650695910072f);
    const u64 C1 = pk(0.6931471805599453f,   0.6931471805599453f);
    const u64 ONE = pk(1.0f, 1.0f);

    u64 acc0 = 0ull, acc1 = 0ull;   // packed {lo,hi} fp32 accumulators (0.0f,0.0f)

#pragma unroll 8
    for (int j = 0; j < NQ; j++) {
        ulonglong2 A = sA[j], B = sB[j], C = sC[j];
        u64 dx, dy, dz, d2, e2, x, t, fi, f, p;

        ADD2(dx, A.x, nX);                // px - tx   (pair)
        ADD2(dy, A.y, nY);
        ADD2(dz, B.x, nZ);
        MUL2(d2, dx, dx);
        FMA2(d2, dy, dy, d2);             // dist_xy
        FMA2(x,  B.y, d2, C.y);           // -a*dxy + c
        MUL2(e2, dz, dz);
        FMA2(x,  C.x, e2, x);             // + (-bz)*dz^2    (log2 domain)

        // packed 2^x: magic-number range reduction, all on fma pipe
        ADD2(t,  x, MAG);                 // rn -> nearest int in mantissa
        ADD2(fi, t, NMAG);                // integer-valued float
        FMA2(f,  fi, NONE, x);            // f = x - fi  in [-0.5, 0.5]
        FMA2(p, C4, f, C3);
        FMA2(p, p,  f, C2);
        FMA2(p, p,  f, C1);
        FMA2(p, p,  f, ONE);

        // exponent scale on the ALU pipe.
        // d = bits(t) - 0x4B3FFF81 == (k + 127) when t is inside the magic
        // window; every out-of-window case (x < -127, huge-negative x making
        // t<=0, etc.) lands outside [0,254] and maps to scale = 0.
        unsigned lo = (unsigned)t;
        unsigned hi = (unsigned)(t >> 32);
        unsigned d0 = lo - 0x4B3FFF81u;
        unsigned d1 = hi - 0x4B3FFF81u;
        unsigned s0 = (d0 <= 254u) ? (d0 << 23) : 0u;
        unsigned s1 = (d1 <= 254u) ? (d1 << 23) : 0u;
        u64 sc = (u64)s0 | ((u64)s1 << 32);

        if (j & 1) { FMA2(acc1, p, sc, acc1); }
        else       { FMA2(acc0, p, sc, acc0); }
    }

    float a0 = __uint_as_float((unsigned)acc0);
    float a1 = __uint_as_float((unsigned)(acc0 >> 32));
    float a2 = __uint_as_float((unsigned)acc1);
    float a3 = __uint_as_float((unsigned)(acc1 >> 32));
    g_part[ch][b * MM + m] = (a0 + a1) + (a2 + a3);
}

// ---------------- reduce stage A: 64 blocks, one -ln(S) per thread ----------
__global__ __launch_bounds__(256) void gmm_red_kernel() {
    __shared__ float red[256];
    const int tid = threadIdx.x;
    const int i = blockIdx.x * 256 + tid;      // 0 .. BB*MM-1  (16384 total)
    float s = 0.0f;
#pragma unroll
    for (int c = 0; c < NCHUNK; c++) s += g_part[c][i];
    red[tid] = -__logf(s);                     // nll = -ln(sum e^lp)
    __syncthreads();
    for (int st = 128; st > 0; st >>= 1) {
        if (tid < st) red[tid] += red[tid + st];
        __syncthreads();
    }
    if (tid == 0) g_red[blockIdx.x] = red[0];
}

// ---------------- reduce stage B: combine 64 block sums, mean ---------------
__global__ void gmm_fin_kernel(float* __restrict__ out) {
    __shared__ float red[RED_BLOCKS];
    const int tid = threadIdx.x;
    red[tid] = g_red[tid];
    __syncthreads();
    for (int st = RED_BLOCKS / 2; st > 0; st >>= 1) {
        if (tid < st) red[tid] += red[tid + st];
        __syncthreads();
    }
    if (tid == 0) out[0] = red[0] * (1.0f / (BB * MM));
}

extern "C" void kernel_launch(void* const* d_in, const int* in_sizes, int n_in,
                              void* d_out, int out_size) {
    const float* pred_xyz   = (const float*)d_in[0];  // [B, N, 3]
    const float* pred_sigma = (const float*)d_in[1];  // [B, N, 2]
    const float* target     = (const float*)d_in[2];  // [B, M, 3]
    float* out = (float*)d_out;

    prep_kernel<<<(BB * NN / 2 + 255) / 256, 256>>>(pred_xyz, pred_sigma);

    dim3 grid(MM / MT, NCHUNK, BB);
    gmm_main_kernel<<<grid, MT>>>(target);

    gmm_red_kernel<<<RED_BLOCKS, 256>>>();
    gmm_fin_kernel<<<1, RED_BLOCKS>>>(out);
}

// round 5
// speedup vs baseline: 1.8175x; 1.1902x over previous
#include <cuda_runtime.h>
#include <cuda_bf16.h>
#include <cstdint>

typedef unsigned long long u64;

#define BB 4
#define NN 4096
#define MM 4096
#define MT 256            // threads per block == m's per block
#define NT 256            // n's per chunk == block size (1 n per thread in prep)
#define NQ (NT / 2)       // packed pairs per chunk
#define NCHUNK (NN / NT)  // 16
#define RED_BLOCKS 64

#define EPSF     1e-8f
#define INV_LN2  1.4426950408889634f
// 1.5 * ln(2*3.14159)  (reference uses pi = 3.14159)
#define C_OFF    2.7568143383208773f

__device__ float g_part[NCHUNK][BB * MM];
__device__ float g_red[RED_BLOCKS];
__device__ unsigned g_count = 0;

// ---------------- packed f32x2 primitives ----------------
#define ADD2(d, a, b)    asm("add.rn.f32x2 %0, %1, %2;"      : "=l"(d) : "l"(a), "l"(b))
#define MUL2(d, a, b)    asm("mul.rn.f32x2 %0, %1, %2;"      : "=l"(d) : "l"(a), "l"(b))
#define FMA2(d, a, b, c) asm("fma.rn.f32x2 %0, %1, %2, %3;"  : "=l"(d) : "l"(a), "l"(b), "l"(c))

__device__ __forceinline__ u64 pk(float lo, float hi) {
    u64 r;
    asm("mov.b64 %0, {%1, %2};" : "=l"(r) : "f"(lo), "f"(hi));
    return r;
}

// ---------------- main: fused prep + partial sum over one n-chunk ----------
__global__ __launch_bounds__(MT) void gmm_main_kernel(const float* __restrict__ xyz,
                                                      const float* __restrict__ sig,
                                                      const float* __restrict__ target) {
    // per-q packed coefficient pairs: D12={cp,apx} D34={apy,bpz} D56={na,nb}
    __shared__ ulonglong2 sD12[NQ], sD34[NQ], sD56[NQ];

    const int mt = blockIdx.x;     // 0..MM/MT-1
    const int ch = blockIdx.y;     // 0..NCHUNK-1
    const int b  = blockIdx.z;     // 0..BB-1
    const int tid = threadIdx.x;

    // ---- in-block prep: this thread handles n = chunk_base + tid ----
    {
        const int n = b * NN + ch * NT + tid;
        float px = xyz[3 * n + 0], py = xyz[3 * n + 1], pz = xyz[3 * n + 2];
        float sxy = sig[2 * n + 0] + EPSF;
        float sz  = sig[2 * n + 1] + EPSF;
        float a  = __fdividef(0.5f * INV_LN2, sxy);   // log2-domain coefs
        float bz = __fdividef(0.5f * INV_LN2, sz);
        float c  = (-__logf(sxy) - 0.5f * __logf(sz) - C_OFF) * INV_LN2;
        float cp  = c - a * (px * px + py * py) - bz * (pz * pz);
        float apx = 2.0f * a * px;
        float apy = 2.0f * a * py;
        float bpz = 2.0f * bz * pz;

        const int q = tid >> 1, par = tid & 1;
        float* f12 = (float*)sD12;       // [4q]=cp_e [4q+1]=cp_o [4q+2]=apx_e [4q+3]=apx_o
        float* f34 = (float*)sD34;
        float* f56 = (float*)sD56;
        f12[4 * q + 0 + par] = cp;
        f12[4 * q + 2 + par] = apx;
        f34[4 * q + 0 + par] = apy;
        f34[4 * q + 2 + par] = bpz;
        f56[4 * q + 0 + par] = -a;
        f56[4 * q + 2 + par] = -bz;
    }

    // ---- per-m values ----
    const int m = mt * MT + tid;
    const float* tp = target + ((size_t)b * MM + m) * 3;
    const float tx = tp[0], ty = tp[1], tz = tp[2];
    const u64 TX  = pk(tx, tx);
    const u64 TY  = pk(ty, ty);
    const u64 TZ  = pk(tz, tz);
    const u64 ST  = pk(tx * tx + ty * ty, tx * tx + ty * ty);
    const u64 TZ2 = pk(tz * tz, tz * tz);

    __syncthreads();

    // packed constants
    const u64 MAG  = pk(12582912.0f, 12582912.0f);    // 2^23 + 2^22
    const u64 NMAG = pk(-12582912.0f, -12582912.0f);
    const u64 NONE = pk(-1.0f, -1.0f);
    // deg-3 economized minimax-ish for 2^f on [-0.5,0.5], max rel err ~6e-5
    const u64 K3 = pk(0.0559208f, 0.0559208f);
    const u64 K2 = pk(0.2426310f, 0.2426310f);
    const u64 K1 = pk(0.6931211f, 0.6931211f);
    const u64 K0 = pk(0.9999646f, 0.9999646f);

    u64 acc0 = 0ull, acc1 = 0ull;   // packed fp32 accumulators {0.0f,0.0f}

#pragma unroll 8
    for (int j = 0; j < NQ; j++) {
        ulonglong2 D12 = sD12[j], D34 = sD34[j], D56 = sD56[j];
        u64 x, t, fi, f, p;

        FMA2(x, D12.y, TX, D12.x);        // cp + apx*tx
        FMA2(x, D34.x, TY, x);            // + apy*ty
        FMA2(x, D34.y, TZ, x);            // + bpz*tz
        FMA2(x, D56.x, ST, x);            // - a*|txy|^2
        FMA2(x, D56.y, TZ2, x);           // - bz*tz^2      (x = lp/ln2)

        // packed 2^x: magic-number range reduction on fma pipe
        ADD2(t,  x, MAG);                 // rn -> nearest int in mantissa
        ADD2(fi, t, NMAG);                // integer-valued float
        FMA2(f,  fi, NONE, x);            // f = x - fi in [-0.5, 0.5]
        FMA2(p, K3, f, K2);
        FMA2(p, p,  f, K1);
        FMA2(p, p,  f, K0);

        // exponent scale on ALU pipe; out-of-window (x<-127, huge-neg) -> 0
        unsigned lo = (unsigned)t;
        unsigned hi = (unsigned)(t >> 32);
        unsigned d0 = lo - 0x4B3FFF81u;   // == k+127 inside window
        unsigned d1 = hi - 0x4B3FFF81u;
        unsigned s0 = (d0 <= 254u) ? (d0 << 23) : 0u;
        unsigned s1 = (d1 <= 254u) ? (d1 << 23) : 0u;
        u64 sc = (u64)s0 | ((u64)s1 << 32);

        if (j & 1) { FMA2(acc1, p, sc, acc1); }
        else       { FMA2(acc0, p, sc, acc0); }
    }

    float a0 = __uint_as_float((unsigned)acc0);
    float a1 = __uint_as_float((unsigned)(acc0 >> 32));
    float a2 = __uint_as_float((unsigned)acc1);
    float a3 = __uint_as_float((unsigned)(acc1 >> 32));
    g_part[ch][b * MM + m] = (a0 + a1) + (a2 + a3);
}

// ---------- reduction: 64 blocks; last block finishes deterministically ----
__global__ __launch_bounds__(256) void gmm_red_kernel(float* __restrict__ out) {
    __shared__ float red[256];
    __shared__ bool amLast;
    const int tid = threadIdx.x;
    const int i = blockIdx.x * 256 + tid;       // 0 .. BB*MM-1
    float s = 0.0f;
#pragma unroll
    for (int c = 0; c < NCHUNK; c++) s += g_part[c][i];
    red[tid] = -__logf(s);                      // nll = -ln(sum e^lp)
    __syncthreads();
    for (int st = 128; st > 0; st >>= 1) {
        if (tid < st) red[tid] += red[tid + st];
        __syncthreads();
    }
    if (tid == 0) {
        g_red[blockIdx.x] = red[0];
        __threadfence();
        unsigned prev = atomicAdd(&g_count, 1u);
        amLast = (prev == RED_BLOCKS - 1);
    }
    __syncthreads();
    if (amLast) {
        // fixed-order final sum: deterministic
        if (tid < RED_BLOCKS) red[tid] = g_red[tid];
        __syncthreads();
        for (int st = RED_BLOCKS / 2; st > 0; st >>= 1) {
            if (tid < st) red[tid] += red[tid + st];
            __syncthreads();
        }
        if (tid == 0) {
            out[0] = red[0] * (1.0f / (BB * MM));
            g_count = 0;                        // reset for next replay
        }
    }
}

extern "C" void kernel_launch(void* const* d_in, const int* in_sizes, int n_in,
                              void* d_out, int out_size) {
    const float* pred_xyz   = (const float*)d_in[0];  // [B, N, 3]
    const float* pred_sigma = (const float*)d_in[1];  // [B, N, 2]
    const float* target     = (const float*)d_in[2];  // [B, M, 3]
    float* out = (float*)d_out;

    dim3 grid(MM / MT, NCHUNK, BB);
    gmm_main_kernel<<<grid, MT>>>(pred_xyz, pred_sigma, target);

    gmm_red_kernel<<<RED_BLOCKS, 256>>>(out);
}

// round 6
// speedup vs baseline: 2.0308x; 1.1174x over previous
#include <cuda_runtime.h>
#include <cuda_bf16.h>
#include <cstdint>

typedef unsigned long long u64;

#define BB 4
#define NN 4096
#define MM 4096
#define MT 256            // threads per block == m's per block
#define NT 512            // n's per chunk
#define NQ (NT / 2)       // packed pairs per chunk
#define NCHUNK (NN / NT)  // 8
#define RED_BLOCKS 128
#define RED_T 128

#define EPSF     1e-8f
#define INV_LN2  1.4426950408889634f
// 1.5 * ln(2*3.14159)  (reference uses pi = 3.14159)
#define C_OFF    2.7568143383208773f

__device__ float g_part[NCHUNK][BB * MM];
__device__ float g_red[RED_BLOCKS];
__device__ unsigned g_count = 0;

// ---------------- packed f32x2 primitives ----------------
#define FMA2(d, a, b, c) asm("fma.rn.f32x2 %0, %1, %2, %3;"  : "=l"(d) : "l"(a), "l"(b), "l"(c))

__device__ __forceinline__ u64 pk(float lo, float hi) {
    u64 r;
    asm("mov.b64 %0, {%1, %2};" : "=l"(r) : "f"(lo), "f"(hi));
    return r;
}

__device__ __forceinline__ float ex2f(float x) {
    float r;
    asm("ex2.approx.f32 %0, %1;" : "=f"(r) : "f"(x));
    return r;
}

// ---------------- main: fused prep + partial sum over one n-chunk ----------
__global__ __launch_bounds__(MT) void gmm_main_kernel(const float* __restrict__ xyz,
                                                      const float* __restrict__ sig,
                                                      const float* __restrict__ target) {
    // per-q packed coefficient pairs: D12={cp,apx} D34={apy,bpz} D56={na,nb}
    __shared__ ulonglong2 sD12[NQ], sD34[NQ], sD56[NQ];

    const int mt = blockIdx.x;     // 0..MM/MT-1
    const int ch = blockIdx.y;     // 0..NCHUNK-1
    const int b  = blockIdx.z;     // 0..BB-1
    const int tid = threadIdx.x;

    // ---- in-block prep: each thread preps NT/MT = 2 n's ----
    for (int jj = tid; jj < NT; jj += MT) {
        const int n = b * NN + ch * NT + jj;
        float px = xyz[3 * n + 0], py = xyz[3 * n + 1], pz = xyz[3 * n + 2];
        float sxy = sig[2 * n + 0] + EPSF;
        float sz  = sig[2 * n + 1] + EPSF;
        float a  = __fdividef(0.5f * INV_LN2, sxy);   // log2-domain coefs
        float bz = __fdividef(0.5f * INV_LN2, sz);
        float c  = (-__logf(sxy) - 0.5f * __logf(sz) - C_OFF) * INV_LN2;
        float cp  = c - a * (px * px + py * py) - bz * (pz * pz);
        float apx = 2.0f * a * px;
        float apy = 2.0f * a * py;
        float bpz = 2.0f * bz * pz;

        const int q = jj >> 1, par = jj & 1;
        float* f12 = (float*)sD12;       // lanes: [4q+0/1]=cp_{e,o} [4q+2/3]=apx_{e,o}
        float* f34 = (float*)sD34;
        float* f56 = (float*)sD56;
        f12[4 * q + 0 + par] = cp;
        f12[4 * q + 2 + par] = apx;
        f34[4 * q + 0 + par] = apy;
        f34[4 * q + 2 + par] = bpz;
        f56[4 * q + 0 + par] = -a;
        f56[4 * q + 2 + par] = -bz;
    }

    // ---- per-m values ----
    const int m = mt * MT + tid;
    const float* tp = target + ((size_t)b * MM + m) * 3;
    const float tx = tp[0], ty = tp[1], tz = tp[2];
    const u64 TX  = pk(tx, tx);
    const u64 TY  = pk(ty, ty);
    const u64 TZ  = pk(tz, tz);
    const u64 ST  = pk(tx * tx + ty * ty, tx * tx + ty * ty);
    const u64 TZ2 = pk(tz * tz, tz * tz);

    __syncthreads();

    float s0 = 0.0f, s1 = 0.0f;

#pragma unroll 8
    for (int j = 0; j < NQ; j++) {
        ulonglong2 D12 = sD12[j], D34 = sD34[j], D56 = sD56[j];
        u64 x;

        FMA2(x, D12.y, TX, D12.x);        // cp + apx*tx
        FMA2(x, D34.x, TY, x);            // + apy*ty
        FMA2(x, D34.y, TZ, x);            // + bpz*tz
        FMA2(x, D56.x, ST, x);            // - a*|txy|^2
        FMA2(x, D56.y, TZ2, x);           // - bz*tz^2      (x = lp/ln2, packed)

        float xlo, xhi;
        asm("mov.b64 {%0, %1}, %2;" : "=f"(xlo), "=f"(xhi) : "l"(x));
        // MUFU pipe: exp2; flushes huge-negative to 0 natively
        s0 += ex2f(xlo);
        s1 += ex2f(xhi);
    }
    g_part[ch][b * MM + m] = s0 + s1;
}

// ---------- reduction: 128 blocks; last block finishes deterministically ----
__global__ __launch_bounds__(RED_T) void gmm_red_kernel(float* __restrict__ out) {
    __shared__ float red[RED_T];
    __shared__ bool amLast;
    const int tid = threadIdx.x;
    const int i = blockIdx.x * RED_T + tid;     // 0 .. BB*MM-1
    float s = 0.0f;
#pragma unroll
    for (int c = 0; c < NCHUNK; c++) s += g_part[c][i];
    red[tid] = -__logf(s);                      // nll = -ln(sum e^lp)
    __syncthreads();
    for (int st = RED_T / 2; st > 0; st >>= 1) {
        if (tid < st) red[tid] += red[tid + st];
        __syncthreads();
    }
    if (tid == 0) {
        g_red[blockIdx.x] = red[0];
        __threadfence();
        unsigned prev = atomicAdd(&g_count, 1u);
        amLast = (prev == RED_BLOCKS - 1);
    }
    __syncthreads();
    if (amLast) {
        red[tid] = g_red[tid];                  // RED_T == RED_BLOCKS
        __syncthreads();
        for (int st = RED_BLOCKS / 2; st > 0; st >>= 1) {
            if (tid < st) red[tid] += red[tid + st];
            __syncthreads();
        }
        if (tid == 0) {
            out[0] = red[0] * (1.0f / (BB * MM));
            g_count = 0;                        // reset for next replay
        }
    }
}

extern "C" void kernel_launch(void* const* d_in, const int* in_sizes, int n_in,
                              void* d_out, int out_size) {
    const float* pred_xyz   = (const float*)d_in[0];  // [B, N, 3]
    const float* pred_sigma = (const float*)d_in[1];  // [B, N, 2]
    const float* target     = (const float*)d_in[2];  // [B, M, 3]
    float* out = (float*)d_out;

    dim3 grid(MM / MT, NCHUNK, BB);
    gmm_main_kernel<<<grid, MT>>>(pred_xyz, pred_sigma, target);

    gmm_red_kernel<<<RED_BLOCKS, RED_T>>>(out);
}